// round 5
// baseline (speedup 1.0000x reference)
#include <cuda_runtime.h>
#include <cstdint>
#include <math.h>

#define NN   1048576
#define EE   4194304
#define BB   2048
#define DIM  32
#define FXD  55
#define OUTD 128
#define SEQ  1000
#define EMBD 128
#define NF   32
#define KW   8
#define LCONV 121
#define BN_EPS 1e-5f

// ---------------- device scratch (static, allowed) ----------------
// g_agg doubles as: (a) neighbor-sum accumulator, (b) MLP output buffer.
// Safe because each MLP thread reads its full agg row into registers before
// writing its output row at the same address.
__device__ __align__(16) float g_h[(size_t)NN * DIM];     // layer input  (128MB)
__device__ __align__(16) float g_agg[(size_t)NN * DIM];   // agg / mlp-out (128MB)
__device__ __align__(16) float g_Wt[SEQ * 256];           // transposed conv_w [c][f*8+k]
__device__ __align__(16) float g_S[(size_t)BB * 26 * 256];// per-graph bucket sums
__device__ __align__(16) float g_conv[(size_t)BB * NF * LCONV];
__device__ __align__(16) float g_xj[(size_t)BB * 256];    // [xdv | xtv]
__device__ __align__(16) float g_z1[(size_t)BB * 1024];
__device__ __align__(16) float g_z2[(size_t)BB * 256];
__device__ __align__(16) float g_pool[(size_t)BB * DIM];
__device__ __align__(16) float g_cnt[BB];
__device__ float g_sum[DIM];
__device__ float g_sq[DIM];
__device__ float g_binv[DIM];
__device__ float g_bsh[DIM];

// ---------------- zero init ----------------
__global__ void k_zero_all() {
    long long i = (long long)blockIdx.x * blockDim.x + threadIdx.x;
    float4 z = make_float4(0.f, 0.f, 0.f, 0.f);
    if (i < (long long)NN * 8) ((float4*)g_agg)[i] = z;
    if (i < DIM) { g_sum[i] = 0.f; g_sq[i] = 0.f; }
    if (i < BB * 8) ((float4*)g_pool)[i] = z;
    if (i < BB) g_cnt[i] = 0.f;
}

// ---------------- graph branch ----------------
// layer-1 projection: h = xd @ w1a   (N x 32); bias added later in k_mlp1b
__global__ void k_proj1(const float* __restrict__ xd, const float* __restrict__ w1a) {
    __shared__ float sWa[FXD * DIM];
    for (int i = threadIdx.x; i < FXD * DIM; i += blockDim.x) sWa[i] = w1a[i];
    __syncthreads();
    long long r = (long long)blockIdx.x * blockDim.x + threadIdx.x;
    if (r >= NN) return;
    float acc[DIM];
#pragma unroll
    for (int j = 0; j < DIM; j++) acc[j] = 0.f;
    const float* xr = xd + r * FXD;
    for (int i = 0; i < FXD; i++) {
        float xi = xr[i];
#pragma unroll
        for (int j = 0; j < DIM; j++) acc[j] += xi * sWa[i * DIM + j];
    }
    float4* ho = (float4*)(g_h + r * DIM);
#pragma unroll
    for (int j = 0; j < 8; j++) {
        float4 o;
        o.x = acc[4 * j + 0]; o.y = acc[4 * j + 1];
        o.z = acc[4 * j + 2]; o.w = acc[4 * j + 3];
        ho[j] = o;
    }
}

// scatter for all layers: h (32-dim) -> agg (32-dim); edge_index is int32
__global__ void k_scatter(const int* __restrict__ ei) {
    long long t = (long long)blockIdx.x * blockDim.x + threadIdx.x;
    if (t >= (long long)EE * 8) return;
    int q = (int)(t & 7);
    long long e = t >> 3;
    int src = ei[e] & (NN - 1);
    int dst = ei[(long long)EE + e] & (NN - 1);
    float4 v = ((const float4*)g_h)[(long long)src * 8 + q];
    float* ap = g_agg + (long long)dst * DIM + q * 4;
    atomicAdd(ap + 0, v.x);
    atomicAdd(ap + 1, v.y);
    atomicAdd(ap + 2, v.z);
    atomicAdd(ap + 3, v.w);
}

// layer-1 second half: agg <- relu(relu(h + agg + b1a) @ w1b + b1b)   (in place)
__global__ void k_mlp1b(const float* __restrict__ b1a,
                        const float* __restrict__ w1b, const float* __restrict__ b1b) {
    __shared__ float sWb[DIM * DIM];
    __shared__ float sBa[DIM];
    __shared__ float sBb[DIM];
    for (int i = threadIdx.x; i < DIM * DIM; i += blockDim.x) sWb[i] = w1b[i];
    if (threadIdx.x < DIM) { sBa[threadIdx.x] = b1a[threadIdx.x]; sBb[threadIdx.x] = b1b[threadIdx.x]; }
    __syncthreads();
    long long r = (long long)blockIdx.x * blockDim.x + threadIdx.x;
    if (r >= NN) return;
    float g[DIM];
    const float4* hr = (const float4*)(g_h + r * DIM);
    const float4* ar = (const float4*)(g_agg + r * DIM);
#pragma unroll
    for (int j = 0; j < 8; j++) {
        float4 a = hr[j], b = ar[j];
        g[4 * j + 0] = fmaxf(a.x + b.x + sBa[4 * j + 0], 0.f);
        g[4 * j + 1] = fmaxf(a.y + b.y + sBa[4 * j + 1], 0.f);
        g[4 * j + 2] = fmaxf(a.z + b.z + sBa[4 * j + 2], 0.f);
        g[4 * j + 3] = fmaxf(a.w + b.w + sBa[4 * j + 3], 0.f);
    }
    float m[DIM];
#pragma unroll
    for (int j = 0; j < DIM; j++) m[j] = sBb[j];
#pragma unroll
    for (int i = 0; i < DIM; i++)
#pragma unroll
        for (int j = 0; j < DIM; j++) m[j] += g[i] * sWb[i * DIM + j];
    float4* mo = (float4*)(g_agg + r * DIM);
#pragma unroll
    for (int j = 0; j < 8; j++) {
        float4 o;
        o.x = fmaxf(m[4 * j + 0], 0.f);
        o.y = fmaxf(m[4 * j + 1], 0.f);
        o.z = fmaxf(m[4 * j + 2], 0.f);
        o.w = fmaxf(m[4 * j + 3], 0.f);
        mo[j] = o;
    }
}

// layers 2-5 MLP: agg <- relu(relu((h+agg)@wa+ba)@wb+bb)   (in place)
__global__ void k_mlp(const float* __restrict__ wa, const float* __restrict__ ba,
                      const float* __restrict__ wb, const float* __restrict__ bb) {
    __shared__ float sWa[DIM * DIM];
    __shared__ float sWb[DIM * DIM];
    __shared__ float sBa[DIM];
    __shared__ float sBb[DIM];
    for (int i = threadIdx.x; i < DIM * DIM; i += blockDim.x) { sWa[i] = wa[i]; sWb[i] = wb[i]; }
    if (threadIdx.x < DIM) { sBa[threadIdx.x] = ba[threadIdx.x]; sBb[threadIdx.x] = bb[threadIdx.x]; }
    __syncthreads();
    long long r = (long long)blockIdx.x * blockDim.x + threadIdx.x;
    if (r >= NN) return;
    float xin[DIM];
    const float4* hr = (const float4*)(g_h + r * DIM);
    const float4* ar = (const float4*)(g_agg + r * DIM);
#pragma unroll
    for (int j = 0; j < 8; j++) {
        float4 a = hr[j], b = ar[j];
        xin[4 * j + 0] = a.x + b.x;
        xin[4 * j + 1] = a.y + b.y;
        xin[4 * j + 2] = a.z + b.z;
        xin[4 * j + 3] = a.w + b.w;
    }
    float g[DIM];
#pragma unroll
    for (int j = 0; j < DIM; j++) g[j] = sBa[j];
#pragma unroll
    for (int i = 0; i < DIM; i++)
#pragma unroll
        for (int j = 0; j < DIM; j++) g[j] += xin[i] * sWa[i * DIM + j];
    float m[DIM];
#pragma unroll
    for (int j = 0; j < DIM; j++) { g[j] = fmaxf(g[j], 0.f); m[j] = sBb[j]; }
#pragma unroll
    for (int i = 0; i < DIM; i++)
#pragma unroll
        for (int j = 0; j < DIM; j++) m[j] += g[i] * sWb[i * DIM + j];
    float4* mo = (float4*)(g_agg + r * DIM);
#pragma unroll
    for (int j = 0; j < 8; j++) {
        float4 o;
        o.x = fmaxf(m[4 * j + 0], 0.f);
        o.y = fmaxf(m[4 * j + 1], 0.f);
        o.z = fmaxf(m[4 * j + 2], 0.f);
        o.w = fmaxf(m[4 * j + 3], 0.f);
        mo[j] = o;
    }
}

// per-channel sum & sumsq over g_agg (mlp output)
__global__ void k_stats() {
    __shared__ float sS[DIM];
    __shared__ float sQ[DIM];
    if (threadIdx.x < DIM) { sS[threadIdx.x] = 0.f; sQ[threadIdx.x] = 0.f; }
    __syncthreads();
    int q = threadIdx.x & 7;
    float4 s = make_float4(0.f, 0.f, 0.f, 0.f);
    float4 sq = make_float4(0.f, 0.f, 0.f, 0.f);
    long long stride = (long long)gridDim.x * blockDim.x;  // multiple of 8
    for (long long i = (long long)blockIdx.x * blockDim.x + threadIdx.x; i < (long long)NN * 8; i += stride) {
        float4 v = ((const float4*)g_agg)[i];
        s.x += v.x; s.y += v.y; s.z += v.z; s.w += v.w;
        sq.x += v.x * v.x; sq.y += v.y * v.y; sq.z += v.z * v.z; sq.w += v.w * v.w;
    }
    atomicAdd(&sS[q * 4 + 0], s.x); atomicAdd(&sS[q * 4 + 1], s.y);
    atomicAdd(&sS[q * 4 + 2], s.z); atomicAdd(&sS[q * 4 + 3], s.w);
    atomicAdd(&sQ[q * 4 + 0], sq.x); atomicAdd(&sQ[q * 4 + 1], sq.y);
    atomicAdd(&sQ[q * 4 + 2], sq.z); atomicAdd(&sQ[q * 4 + 3], sq.w);
    __syncthreads();
    if (threadIdx.x < DIM) {
        atomicAdd(&g_sum[threadIdx.x], sS[threadIdx.x]);
        atomicAdd(&g_sq[threadIdx.x], sQ[threadIdx.x]);
    }
}

__global__ void k_bnfin(const float* __restrict__ bng, const float* __restrict__ bnb, int layer) {
    int j = threadIdx.x;
    if (j >= DIM) return;
    float s = g_sum[j], ss = g_sq[j];
    float mu = s / (float)NN;
    float var = ss / (float)NN - mu * mu;
    float inv = bng[layer * DIM + j] * rsqrtf(var + BN_EPS);
    g_binv[j] = inv;
    g_bsh[j] = bnb[layer * DIM + j] - mu * inv;
    g_sum[j] = 0.f; g_sq[j] = 0.f;
}

// h = agg*inv+shift ; then zero agg for next layer
__global__ void k_norm() {
    long long i = (long long)blockIdx.x * blockDim.x + threadIdx.x;
    if (i >= (long long)NN * 8) return;
    int q = (int)(i & 7);
    float4 v = ((const float4*)g_agg)[i];
    float4 o;
    o.x = v.x * g_binv[q * 4 + 0] + g_bsh[q * 4 + 0];
    o.y = v.y * g_binv[q * 4 + 1] + g_bsh[q * 4 + 1];
    o.z = v.z * g_binv[q * 4 + 2] + g_bsh[q * 4 + 2];
    o.w = v.w * g_binv[q * 4 + 3] + g_bsh[q * 4 + 3];
    ((float4*)g_h)[i] = o;
    ((float4*)g_agg)[i] = make_float4(0.f, 0.f, 0.f, 0.f);
}

// global mean pool: sums + counts; batch is int32
__global__ void k_pool(const int* __restrict__ batch) {
    long long t = (long long)blockIdx.x * blockDim.x + threadIdx.x;
    if (t >= (long long)NN * 8) return;
    long long node = t >> 3;
    int q = (int)(t & 7);
    float4 v = ((const float4*)g_h)[t];
    int g = batch[node] & (BB - 1);
    float* pp = g_pool + (long long)g * DIM + q * 4;
    atomicAdd(pp + 0, v.x);
    atomicAdd(pp + 1, v.y);
    atomicAdd(pp + 2, v.z);
    atomicAdd(pp + 3, v.w);
    if (q == 0) atomicAdd(&g_cnt[g], 1.f);
}

// xdv = relu(pooled/cnt @ fcd_w + fcd_b) -> g_xj[:, 0:128]
__global__ void k_xdv(const float* __restrict__ fcd_w, const float* __restrict__ fcd_b) {
    __shared__ float sp[DIM];
    int b = blockIdx.x;
    if (threadIdx.x < DIM) {
        float c = g_cnt[b];
        sp[threadIdx.x] = g_pool[(long long)b * DIM + threadIdx.x] / fmaxf(c, 1.f);
    }
    __syncthreads();
    int o = threadIdx.x;  // 128 threads
    float acc = fcd_b[o];
#pragma unroll
    for (int i = 0; i < DIM; i++) acc += sp[i] * fcd_w[i * OUTD + o];
    g_xj[(long long)b * 256 + o] = fmaxf(acc, 0.f);
}

// ---------------- protein branch ----------------
// Wt[c][f*8+k] = conv_w[f][c][k]
__global__ void k_wt(const float* __restrict__ conv_w) {
    int t = blockIdx.x * blockDim.x + threadIdx.x;
    if (t >= SEQ * 256) return;
    int c = t >> 8;
    int fk = t & 255;
    int f = fk >> 3, k = fk & 7;
    g_Wt[t] = conv_w[(f * SEQ + c) * KW + k];
}

// S[b][v][fk] = sum_{c: xt[b,c]==v} Wt[c][fk]  (counting sort per graph); xt is int32
__global__ void k_bucketS(const int* __restrict__ xt) {
    __shared__ int cnt[26];
    __shared__ int off[27];
    __shared__ int woff[26];
    __shared__ unsigned short perm[SEQ];
    int b = blockIdx.x;
    int tid = threadIdx.x;
    if (tid < 26) cnt[tid] = 0;
    __syncthreads();
    const int* xr = xt + (long long)b * SEQ;
    for (int c = tid; c < SEQ; c += 256) {
        int v = xr[c]; v = v < 0 ? 0 : (v > 25 ? 25 : v);
        atomicAdd(&cnt[v], 1);
    }
    __syncthreads();
    if (tid == 0) {
        int a = 0;
        for (int v = 0; v < 26; v++) { off[v] = a; a += cnt[v]; }
        off[26] = a;
    }
    __syncthreads();
    if (tid < 26) woff[tid] = off[tid];
    __syncthreads();
    for (int c = tid; c < SEQ; c += 256) {
        int v = xr[c]; v = v < 0 ? 0 : (v > 25 ? 25 : v);
        int p = atomicAdd(&woff[v], 1);
        perm[p] = (unsigned short)c;
    }
    __syncthreads();
    int fk = tid;
    float* So = g_S + (long long)b * 26 * 256;
    for (int v = 0; v < 26; v++) {
        float acc = 0.f;
        int e = off[v + 1];
        for (int i = off[v]; i < e; i++)
            acc += g_Wt[(int)perm[i] * 256 + fk];
        So[v * 256 + fk] = acc;
    }
}

// conv[b][f][hh] = conv_b[f] + sum_v sum_k S[b][v][f*8+k] * emb[v][hh+k]
__global__ void k_conv(const float* __restrict__ emb, const float* __restrict__ conv_b) {
    __shared__ float sS[26 * 256];
    __shared__ float sE[26 * EMBD];
    int b = blockIdx.x;
    int tid = threadIdx.x;
    const float* Sb = g_S + (long long)b * 26 * 256;
    for (int i = tid; i < 26 * 256; i += 256) sS[i] = Sb[i];
    for (int i = tid; i < 26 * EMBD; i += 256) sE[i] = emb[i];
    __syncthreads();
    int f = tid >> 3;
    int sub = tid & 7;
    int hh0 = sub * 16;
    int nh = LCONV - hh0; if (nh > 16) nh = 16;
    float cb = conv_b[f];
    float acc[16];
#pragma unroll
    for (int j = 0; j < 16; j++) acc[j] = cb;
    for (int v = 0; v < 26; v++) {
        float sk[8];
#pragma unroll
        for (int k = 0; k < 8; k++) sk[k] = sS[v * 256 + f * 8 + k];
        float ev[23];
#pragma unroll
        for (int j = 0; j < 23; j++) ev[j] = (j < nh + 7) ? sE[v * EMBD + hh0 + j] : 0.f;
#pragma unroll
        for (int j = 0; j < 16; j++) {
            if (j < nh) {
                float a = acc[j];
#pragma unroll
                for (int k = 0; k < 8; k++) a += sk[k] * ev[j + k];
                acc[j] = a;
            }
        }
    }
    for (int j = 0; j < nh; j++)
        g_conv[(long long)b * (NF * LCONV) + f * LCONV + hh0 + j] = acc[j];
}

// ---------------- generic tiled GEMM with device-side buffer selection ----------------
// a_id: 0=g_conv 1=g_xj 2=g_z1 ; c_id: 0=g_xj+128 1=g_z1 2=g_z2
__global__ void k_gemm(int a_id, int lda,
                       const float* __restrict__ W, const float* __restrict__ bias,
                       int c_id, int ldc, int K, int N2, int dorelu) {
    const float* A = (a_id == 0) ? g_conv : (a_id == 1) ? g_xj : g_z1;
    float* C = (c_id == 0) ? (g_xj + 128) : (c_id == 1) ? g_z1 : g_z2;
    __shared__ float As[16][33];
    int m0 = blockIdx.x * 16;
    int n0 = blockIdx.y * 128;
    int col = threadIdx.x & 127;
    int rg = threadIdx.x >> 7;
    float acc[8];
#pragma unroll
    for (int r = 0; r < 8; r++) acc[r] = 0.f;
    for (int k0 = 0; k0 < K; k0 += 32) {
#pragma unroll
        for (int l = 0; l < 2; l++) {
            int idx = threadIdx.x + 256 * l;
            int rr = idx >> 5, kk = idx & 31;
            As[rr][kk] = A[(long long)(m0 + rr) * lda + k0 + kk];
        }
        __syncthreads();
#pragma unroll 8
        for (int kk = 0; kk < 32; kk++) {
            float w = W[(long long)(k0 + kk) * N2 + n0 + col];
#pragma unroll
            for (int r = 0; r < 8; r++) acc[r] += As[rg * 8 + r][kk] * w;
        }
        __syncthreads();
    }
    float bv = bias[n0 + col];
#pragma unroll
    for (int r = 0; r < 8; r++) {
        float v = acc[r] + bv;
        if (dorelu) v = fmaxf(v, 0.f);
        C[(long long)(m0 + rg * 8 + r) * ldc + n0 + col] = v;
    }
}

// out[b] = z2[b,:] . c3w + c3b
__global__ void k_final(const float* __restrict__ c3w, const float* __restrict__ c3b,
                        float* __restrict__ out) {
    int gwarp = (blockIdx.x * blockDim.x + threadIdx.x) >> 5;
    int lane = threadIdx.x & 31;
    if (gwarp >= BB) return;
    float acc = 0.f;
    for (int i = lane; i < 256; i += 32) acc += g_z2[(long long)gwarp * 256 + i] * c3w[i];
#pragma unroll
    for (int s = 16; s > 0; s >>= 1) acc += __shfl_down_sync(0xffffffffu, acc, s);
    if (lane == 0) out[gwarp] = acc + c3b[0];
}

// ---------------- launch ----------------
extern "C" void kernel_launch(void* const* d_in, const int* in_sizes, int n_in,
                              void* d_out, int out_size) {
    (void)in_sizes; (void)n_in; (void)out_size;
    const float* xd    = (const float*)d_in[0];
    const int*   ei    = (const int*)d_in[1];     // int32 (JAX x64 disabled)
    const int*   batch = (const int*)d_in[2];     // int32
    const int*   xt    = (const int*)d_in[3];     // int32
    const float* w1a = (const float*)d_in[4];
    const float* b1a = (const float*)d_in[5];
    const float* w1b = (const float*)d_in[6];
    const float* b1b = (const float*)d_in[7];
    const float* wa  = (const float*)d_in[8];
    const float* ba  = (const float*)d_in[9];
    const float* wb  = (const float*)d_in[10];
    const float* bb  = (const float*)d_in[11];
    const float* bng = (const float*)d_in[12];
    const float* bnb = (const float*)d_in[13];
    const float* fcd_w = (const float*)d_in[14];
    const float* fcd_b = (const float*)d_in[15];
    const float* emb   = (const float*)d_in[16];
    const float* conv_w = (const float*)d_in[17];
    const float* conv_b = (const float*)d_in[18];
    const float* fct_w  = (const float*)d_in[19];
    const float* fct_b  = (const float*)d_in[20];
    const float* c1w = (const float*)d_in[21];
    const float* c1b = (const float*)d_in[22];
    const float* c2w = (const float*)d_in[23];
    const float* c2b = (const float*)d_in[24];
    const float* c3w = (const float*)d_in[25];
    const float* c3b = (const float*)d_in[26];
    float* out = (float*)d_out;

    const int T = 256;

    // init
    k_zero_all<<<((long long)NN * 8 + T - 1) / T, T>>>();

    // ---- protein branch ----
    k_wt<<<(SEQ * 256 + T - 1) / T, T>>>(conv_w);
    k_bucketS<<<BB, 256>>>(xt);
    k_conv<<<BB, 256>>>(emb, conv_b);
    // xtv = conv_flat @ fct_w + fct_b  -> g_xj[:,128:256]
    {
        dim3 grid(BB / 16, OUTD / 128);
        k_gemm<<<grid, 256>>>(0, NF * LCONV, fct_w, fct_b, 0, 256, NF * LCONV, OUTD, 0);
    }

    // ---- graph branch ----
    // layer 1: project 55->32 first, then scatter the projection
    k_proj1<<<(NN + T - 1) / T, T>>>(xd, w1a);
    k_scatter<<<((long long)EE * 8 + T - 1) / T, T>>>(ei);
    k_mlp1b<<<(NN + T - 1) / T, T>>>(b1a, w1b, b1b);
    k_stats<<<1024, 256>>>();
    k_bnfin<<<1, 32>>>(bng, bnb, 0);
    k_norm<<<((long long)NN * 8 + T - 1) / T, T>>>();
    // layers 2-5
    for (int l = 0; l < 4; l++) {
        k_scatter<<<((long long)EE * 8 + T - 1) / T, T>>>(ei);
        k_mlp<<<(NN + T - 1) / T, T>>>(wa + (size_t)l * DIM * DIM, ba + (size_t)l * DIM,
                                       wb + (size_t)l * DIM * DIM, bb + (size_t)l * DIM);
        k_stats<<<1024, 256>>>();
        k_bnfin<<<1, 32>>>(bng, bnb, l + 1);
        k_norm<<<((long long)NN * 8 + T - 1) / T, T>>>();
    }
    // pooling + fc1_xd
    k_pool<<<((long long)NN * 8 + T - 1) / T, T>>>(batch);
    k_xdv<<<BB, 128>>>(fcd_w, fcd_b);

    // ---- classifier ----
    {
        dim3 g1(BB / 16, 1024 / 128);
        k_gemm<<<g1, 256>>>(1, 256, c1w, c1b, 1, 1024, 256, 1024, 1);
        dim3 g2(BB / 16, 256 / 128);
        k_gemm<<<g2, 256>>>(2, 1024, c2w, c2b, 2, 256, 1024, 256, 1);
    }
    k_final<<<(BB * 32 + T - 1) / T, T>>>(c3w, c3b, out);
}